// round 4
// baseline (speedup 1.0000x reference)
#include <cuda_runtime.h>
#include <cstdint>
#include <math.h>

#define B_SZ 4
#define S_LEN 4096
#define E_SZ 768
#define H_SZ 64

typedef unsigned long long u64;

// Scratch: Q,K natural [b][s][h]; V transposed [b][h][s].
__device__ float g_q [B_SZ * S_LEN * H_SZ];
__device__ float g_k [B_SZ * S_LEN * H_SZ];
__device__ float g_vt[B_SZ * H_SZ * S_LEN];

// ---- packed fp32 helpers -------------------------------------------------
__device__ __forceinline__ void fma2(u64 &acc, double a, double b) {
    asm("fma.rn.f32x2 %0, %1, %2, %0;"
        : "+l"(acc)
        : "l"(__double_as_longlong(a)), "l"(__double_as_longlong(b)));
}
__device__ __forceinline__ u64 dup2(float v) {
    u64 r; asm("mov.b64 %0, {%1,%1};" : "=l"(r) : "f"(v)); return r;
}
__device__ __forceinline__ void mul2(u64 &acc, u64 s) {
    asm("mul.rn.f32x2 %0, %0, %1;" : "+l"(acc) : "l"(s));
}
__device__ __forceinline__ float2 unpack2(u64 v) {
    float2 f; asm("mov.b64 {%0,%1}, %2;" : "=f"(f.x), "=f"(f.y) : "l"(v)); return f;
}
__device__ __forceinline__ void cp16(uint32_t dst, const float* src) {
    asm volatile("cp.async.cg.shared.global [%0], [%1], 16;" :: "r"(dst), "l"(src));
}

// ---------------------------------------------------------------------------
// Kernel 1: QKV projection. grid=(128,3), 256 thr, >=2 CTAs/SM.
// C[s][h] = sum_e x[s][e] W[h][e].  BM=128, BN=64, BK=32; tile 8x4; f32x2 on E.
// ---------------------------------------------------------------------------
__global__ __launch_bounds__(256, 2) void qkv_kernel(
    const float* __restrict__ x,
    const float* __restrict__ Wq,
    const float* __restrict__ Wk,
    const float* __restrict__ Wv)
{
    const int wsel = blockIdx.y;
    const float* __restrict__ W = (wsel == 0) ? Wq : (wsel == 1) ? Wk : Wv;

    __shared__ float xs[128 * 36];
    __shared__ float ws[64 * 36];

    const int tid = threadIdx.x;
    const int tx = tid & 15;     // h cols: tx + 16j
    const int ty = tid >> 4;     // s rows: 8ty + i
    const int rowBase = blockIdx.x * 128;

    u64 acc[8][4];
#pragma unroll
    for (int i = 0; i < 8; i++)
#pragma unroll
        for (int j = 0; j < 4; j++) acc[i][j] = 0ull;

    for (int kb = 0; kb < E_SZ; kb += 32) {
#pragma unroll
        for (int p = 0; p < 4; p++) {
            int f = p * 256 + tid;
            int r = f >> 3, c = f & 7;
            *reinterpret_cast<float4*>(&xs[r * 36 + 4 * c]) =
                *reinterpret_cast<const float4*>(&x[(size_t)(rowBase + r) * E_SZ + kb + 4 * c]);
        }
#pragma unroll
        for (int p = 0; p < 2; p++) {
            int f = p * 256 + tid;
            int r = f >> 3, c = f & 7;
            *reinterpret_cast<float4*>(&ws[r * 36 + 4 * c]) =
                *reinterpret_cast<const float4*>(&W[(size_t)r * E_SZ + kb + 4 * c]);
        }
        __syncthreads();
#pragma unroll 2
        for (int c = 0; c < 8; c++) {
            double2 xd[8], wd[4];
#pragma unroll
            for (int i = 0; i < 8; i++)
                xd[i] = *reinterpret_cast<const double2*>(&xs[(8 * ty + i) * 36 + 4 * c]);
#pragma unroll
            for (int j = 0; j < 4; j++)
                wd[j] = *reinterpret_cast<const double2*>(&ws[(tx + 16 * j) * 36 + 4 * c]);
#pragma unroll
            for (int i = 0; i < 8; i++)
#pragma unroll
                for (int j = 0; j < 4; j++) {
                    fma2(acc[i][j], xd[i].x, wd[j].x);
                    fma2(acc[i][j], xd[i].y, wd[j].y);
                }
        }
        __syncthreads();
    }

    float r_[8][4];
#pragma unroll
    for (int i = 0; i < 8; i++)
#pragma unroll
        for (int j = 0; j < 4; j++) {
            float2 f = unpack2(acc[i][j]);
            r_[i][j] = f.x + f.y;
        }

    const int b = rowBase >> 12;
    const int s0 = rowBase & 4095;
    if (wsel < 2) {
        float* dst = (wsel == 0) ? g_q : g_k;
#pragma unroll
        for (int i = 0; i < 8; i++)
#pragma unroll
            for (int j = 0; j < 4; j++)
                dst[(size_t)(b * S_LEN + s0 + 8 * ty + i) * H_SZ + tx + 16 * j] = r_[i][j];
    } else {
        // V transposed: g_vt[b][h][s]
#pragma unroll
        for (int j = 0; j < 4; j++) {
            int h = tx + 16 * j;
            float* dst = &g_vt[(size_t)(b * H_SZ + h) * S_LEN + s0 + 8 * ty];
            *reinterpret_cast<float4*>(dst) = make_float4(r_[0][j], r_[1][j], r_[2][j], r_[3][j]);
            *reinterpret_cast<float4*>(dst + 4) = make_float4(r_[4][j], r_[5][j], r_[6][j], r_[7][j]);
        }
    }
}

// ---------------------------------------------------------------------------
// Kernel 2: flash attention, floor(QK^T/8), f32x2-packed GEMMs.
// grid=(32,4), 512 thr, thread tile 4x4 (low regs -> 16 warps/SM).
// Smem (floats): Qs[128*68] @0 | Ks[2][64*68] @8704 | Vt[2][64*68] @17408 |
//                Pb[128*68] @26112.  Total 139264 B (dynamic).
// ---------------------------------------------------------------------------
#define QS_OFF 0
#define KS_OFF 8704
#define VT_OFF 17408
#define PB_OFF 26112
#define BUF_STRIDE 4352
#define SMEM_BYTES (34816 * 4)

__global__ __launch_bounds__(512, 1) void flash_kernel(float* __restrict__ out)
{
    extern __shared__ float sm[];
    const int tid = threadIdx.x;
    const int tx = tid & 15;     // k/h col group: cols tx + 16j
    const int ty = tid >> 4;     // q row group: rows 4ty + i   (ty in 0..31)
    const int b = blockIdx.y;
    const int q0 = blockIdx.x * 128;
    const uint32_t smb = (uint32_t)__cvta_generic_to_shared(sm);

    // prologue: async-load tile 0 (K & V)
#pragma unroll
    for (int p = 0; p < 2; p++) {
        int f = p * 512 + tid;
        int r = f >> 4, c = f & 15;
        cp16(smb + (KS_OFF + r * 68 + 4 * c) * 4,
             &g_k[(size_t)(b * S_LEN + r) * H_SZ + 4 * c]);
        cp16(smb + (VT_OFF + r * 68 + 4 * c) * 4,
             &g_vt[(size_t)(b * H_SZ + r) * S_LEN + 4 * c]);
    }
    asm volatile("cp.async.commit_group;");

    // Q tile: plain vector loads
#pragma unroll
    for (int p = 0; p < 4; p++) {
        int f = p * 512 + tid;
        int r = f >> 4, c = f & 15;
        *reinterpret_cast<float4*>(&sm[QS_OFF + r * 68 + 4 * c]) =
            *reinterpret_cast<const float4*>(&g_q[(size_t)(b * S_LEN + q0 + r) * H_SZ + 4 * c]);
    }

    float m[4], l[4];
    u64 o2[4][4];
#pragma unroll
    for (int i = 0; i < 4; i++) {
        m[i] = -1e30f; l[i] = 0.f;
#pragma unroll
        for (int j = 0; j < 4; j++) o2[i][j] = 0ull;
    }

    for (int t = 0; t < S_LEN / 64; t++) {
        __syncthreads();                     // prev PV / P-buffer fully consumed
        if (t + 1 < S_LEN / 64) {
            const int buf = (t + 1) & 1;
            const int k0n = (t + 1) * 64;
#pragma unroll
            for (int p = 0; p < 2; p++) {
                int f = p * 512 + tid;
                int r = f >> 4, c = f & 15;
                cp16(smb + (KS_OFF + buf * BUF_STRIDE + r * 68 + 4 * c) * 4,
                     &g_k[(size_t)(b * S_LEN + k0n + r) * H_SZ + 4 * c]);
                cp16(smb + (VT_OFF + buf * BUF_STRIDE + r * 68 + 4 * c) * 4,
                     &g_vt[(size_t)(b * H_SZ + r) * S_LEN + k0n + 4 * c]);
            }
            asm volatile("cp.async.commit_group;");
            asm volatile("cp.async.wait_group 1;");
        } else {
            asm volatile("cp.async.wait_group 0;");
        }
        __syncthreads();                     // current K/V tile visible

        const float* Ks = sm + KS_OFF + (t & 1) * BUF_STRIDE;
        const float* Vt = sm + VT_OFF + (t & 1) * BUF_STRIDE;
        float* Pb = sm + PB_OFF;

        // ---- S = Q K^T : pack along h (same accumulation order as before)
        u64 acc[4][4];
#pragma unroll
        for (int i = 0; i < 4; i++)
#pragma unroll
            for (int j = 0; j < 4; j++) acc[i][j] = 0ull;

#pragma unroll 4
        for (int c = 0; c < 16; c++) {
            double2 qd[4], kd[4];
#pragma unroll
            for (int i = 0; i < 4; i++)
                qd[i] = *reinterpret_cast<const double2*>(&sm[QS_OFF + (4 * ty + i) * 68 + 4 * c]);
#pragma unroll
            for (int j = 0; j < 4; j++)
                kd[j] = *reinterpret_cast<const double2*>(&Ks[(tx + 16 * j) * 68 + 4 * c]);
#pragma unroll
            for (int i = 0; i < 4; i++)
#pragma unroll
                for (int j = 0; j < 4; j++) {
                    fma2(acc[i][j], qd[i].x, kd[j].x);
                    fma2(acc[i][j], qd[i].y, kd[j].y);
                }
        }

        // ---- floor + online softmax (row reduction over 16 tx lanes)
#pragma unroll
        for (int i = 0; i < 4; i++) {
            float s[4];
            float rm = -1e30f;
#pragma unroll
            for (int j = 0; j < 4; j++) {
                float2 f = unpack2(acc[i][j]);
                s[j] = floorf((f.x + f.y) * 0.125f);
                rm = fmaxf(rm, s[j]);
            }
#pragma unroll
            for (int d = 1; d < 16; d <<= 1)
                rm = fmaxf(rm, __shfl_xor_sync(0xffffffffu, rm, d));
            float mn = fmaxf(m[i], rm);
            float alpha = __expf(m[i] - mn);
            m[i] = mn;
            float pv[4];
            float rs = 0.f;
#pragma unroll
            for (int j = 0; j < 4; j++) {
                pv[j] = __expf(s[j] - mn);
                rs += pv[j];
            }
#pragma unroll
            for (int d = 1; d < 16; d <<= 1)
                rs += __shfl_xor_sync(0xffffffffu, rs, d);
            l[i] = l[i] * alpha + rs;
            u64 a2 = dup2(alpha);
#pragma unroll
            for (int j = 0; j < 4; j++) mul2(o2[i][j], a2);
#pragma unroll
            for (int j = 0; j < 4; j++)
                Pb[(4 * ty + i) * 68 + tx + 16 * j] = pv[j];
        }
        __syncthreads();                     // P tile complete

        // ---- O += P V : pack along k (same order as before)
#pragma unroll 4
        for (int c = 0; c < 16; c++) {
            double2 pd[4], vd[4];
#pragma unroll
            for (int i = 0; i < 4; i++)
                pd[i] = *reinterpret_cast<const double2*>(&Pb[(4 * ty + i) * 68 + 4 * c]);
#pragma unroll
            for (int j = 0; j < 4; j++)
                vd[j] = *reinterpret_cast<const double2*>(&Vt[(tx + 16 * j) * 68 + 4 * c]);
#pragma unroll
            for (int i = 0; i < 4; i++)
#pragma unroll
                for (int j = 0; j < 4; j++) {
                    fma2(o2[i][j], pd[i].x, vd[j].x);
                    fma2(o2[i][j], pd[i].y, vd[j].y);
                }
        }
    }

    // ---- epilogue
#pragma unroll
    for (int i = 0; i < 4; i++) {
        float inv = 1.0f / l[i];
#pragma unroll
        for (int j = 0; j < 4; j++) {
            float2 f = unpack2(o2[i][j]);
            out[(size_t)(b * S_LEN + q0 + 4 * ty + i) * H_SZ + tx + 16 * j] = (f.x + f.y) * inv;
        }
    }
}

// ---------------------------------------------------------------------------
extern "C" void kernel_launch(void* const* d_in, const int* in_sizes, int n_in,
                              void* d_out, int out_size)
{
    const float* x  = (const float*)d_in[0];
    const float* Wq = (const float*)d_in[1];
    const float* Wk = (const float*)d_in[2];
    const float* Wv = (const float*)d_in[3];
    float* out = (float*)d_out;

    cudaFuncSetAttribute(flash_kernel, cudaFuncAttributeMaxDynamicSharedMemorySize, SMEM_BYTES);

    qkv_kernel<<<dim3(128, 3), 256>>>(x, Wq, Wk, Wv);
    flash_kernel<<<dim3(S_LEN / 128, B_SZ), 512, SMEM_BYTES>>>(out);
}

// round 5
// speedup vs baseline: 1.6325x; 1.6325x over previous
#include <cuda_runtime.h>
#include <cstdint>
#include <math.h>

#define B_SZ 4
#define S_LEN 4096
#define E_SZ 768
#define H_SZ 64

typedef unsigned long long u64;

// Scratch: Q,K natural [b][s][h]; V transposed [b][h][s].
__device__ float g_q [B_SZ * S_LEN * H_SZ];
__device__ float g_k [B_SZ * S_LEN * H_SZ];
__device__ float g_vt[B_SZ * H_SZ * S_LEN];

// ---- packed fp32 helpers -------------------------------------------------
__device__ __forceinline__ void fma2(u64 &acc, double a, double b) {
    asm("fma.rn.f32x2 %0, %1, %2, %0;"
        : "+l"(acc)
        : "l"(__double_as_longlong(a)), "l"(__double_as_longlong(b)));
}
__device__ __forceinline__ u64 dup2(float v) {
    u64 r; asm("mov.b64 %0, {%1,%1};" : "=l"(r) : "f"(v)); return r;
}
__device__ __forceinline__ void mul2(u64 &acc, u64 s) {
    asm("mul.rn.f32x2 %0, %0, %1;" : "+l"(acc) : "l"(s));
}
__device__ __forceinline__ float2 unpack2(u64 v) {
    float2 f; asm("mov.b64 {%0,%1}, %2;" : "=f"(f.x), "=f"(f.y) : "l"(v)); return f;
}
__device__ __forceinline__ void cp16(uint32_t dst, const float* src) {
    asm volatile("cp.async.cg.shared.global [%0], [%1], 16;" :: "r"(dst), "l"(src));
}

// ---------------------------------------------------------------------------
// Kernel 1: QKV projection. grid=(128,3), 256 thr, >=2 CTAs/SM.
// C[s][h] = sum_e x[s][e] W[h][e].  BM=128, BN=64, BK=32; tile 8x4; f32x2 on E.
// ---------------------------------------------------------------------------
__global__ __launch_bounds__(256, 2) void qkv_kernel(
    const float* __restrict__ x,
    const float* __restrict__ Wq,
    const float* __restrict__ Wk,
    const float* __restrict__ Wv)
{
    const int wsel = blockIdx.y;
    const float* __restrict__ W = (wsel == 0) ? Wq : (wsel == 1) ? Wk : Wv;

    __shared__ float xs[128 * 36];
    __shared__ float ws[64 * 36];

    const int tid = threadIdx.x;
    const int tx = tid & 15;     // h cols: tx + 16j
    const int ty = tid >> 4;     // s rows: 8ty + i
    const int rowBase = blockIdx.x * 128;

    u64 acc[8][4];
#pragma unroll
    for (int i = 0; i < 8; i++)
#pragma unroll
        for (int j = 0; j < 4; j++) acc[i][j] = 0ull;

    for (int kb = 0; kb < E_SZ; kb += 32) {
#pragma unroll
        for (int p = 0; p < 4; p++) {
            int f = p * 256 + tid;
            int r = f >> 3, c = f & 7;
            *reinterpret_cast<float4*>(&xs[r * 36 + 4 * c]) =
                *reinterpret_cast<const float4*>(&x[(size_t)(rowBase + r) * E_SZ + kb + 4 * c]);
        }
#pragma unroll
        for (int p = 0; p < 2; p++) {
            int f = p * 256 + tid;
            int r = f >> 3, c = f & 7;
            *reinterpret_cast<float4*>(&ws[r * 36 + 4 * c]) =
                *reinterpret_cast<const float4*>(&W[(size_t)r * E_SZ + kb + 4 * c]);
        }
        __syncthreads();
#pragma unroll 2
        for (int c = 0; c < 8; c++) {
            double2 xd[8], wd[4];
#pragma unroll
            for (int i = 0; i < 8; i++)
                xd[i] = *reinterpret_cast<const double2*>(&xs[(8 * ty + i) * 36 + 4 * c]);
#pragma unroll
            for (int j = 0; j < 4; j++)
                wd[j] = *reinterpret_cast<const double2*>(&ws[(tx + 16 * j) * 36 + 4 * c]);
#pragma unroll
            for (int i = 0; i < 8; i++)
#pragma unroll
                for (int j = 0; j < 4; j++) {
                    fma2(acc[i][j], xd[i].x, wd[j].x);
                    fma2(acc[i][j], xd[i].y, wd[j].y);
                }
        }
        __syncthreads();
    }

    float r_[8][4];
#pragma unroll
    for (int i = 0; i < 8; i++)
#pragma unroll
        for (int j = 0; j < 4; j++) {
            float2 f = unpack2(acc[i][j]);
            r_[i][j] = f.x + f.y;
        }

    const int b = rowBase >> 12;
    const int s0 = rowBase & 4095;
    if (wsel < 2) {
        float* dst = (wsel == 0) ? g_q : g_k;
#pragma unroll
        for (int i = 0; i < 8; i++)
#pragma unroll
            for (int j = 0; j < 4; j++)
                dst[(size_t)(b * S_LEN + s0 + 8 * ty + i) * H_SZ + tx + 16 * j] = r_[i][j];
    } else {
        // V transposed: g_vt[b][h][s]
#pragma unroll
        for (int j = 0; j < 4; j++) {
            int h = tx + 16 * j;
            float* dst = &g_vt[(size_t)(b * H_SZ + h) * S_LEN + s0 + 8 * ty];
            *reinterpret_cast<float4*>(dst) = make_float4(r_[0][j], r_[1][j], r_[2][j], r_[3][j]);
            *reinterpret_cast<float4*>(dst + 4) = make_float4(r_[4][j], r_[5][j], r_[6][j], r_[7][j]);
        }
    }
}

// ---------------------------------------------------------------------------
// Kernel 2: flash attention, floor(QK^T/8), f32x2-packed GEMMs.
// grid=(32,4), 512 thr, thread tile 4x4 (low regs -> 16 warps/SM).
// Smem (floats): Qs[128*68] @0 | Ks[2][64*68] @8704 | Vt[2][64*68] @17408 |
//                Pb[128*68] @26112.  Total 139264 B (dynamic).
// ---------------------------------------------------------------------------
#define QS_OFF 0
#define KS_OFF 8704
#define VT_OFF 17408
#define PB_OFF 26112
#define BUF_STRIDE 4352
#define SMEM_BYTES (34816 * 4)

__global__ __launch_bounds__(512, 1) void flash_kernel(float* __restrict__ out)
{
    extern __shared__ float sm[];
    const int tid = threadIdx.x;
    const int tx = tid & 15;     // k/h col group: cols tx + 16j
    const int ty = tid >> 4;     // q row group: rows 4ty + i   (ty in 0..31)
    const int b = blockIdx.y;
    const int q0 = blockIdx.x * 128;
    const uint32_t smb = (uint32_t)__cvta_generic_to_shared(sm);

    // prologue: async-load tile 0 (K & V)
#pragma unroll
    for (int p = 0; p < 2; p++) {
        int f = p * 512 + tid;
        int r = f >> 4, c = f & 15;
        cp16(smb + (KS_OFF + r * 68 + 4 * c) * 4,
             &g_k[(size_t)(b * S_LEN + r) * H_SZ + 4 * c]);
        cp16(smb + (VT_OFF + r * 68 + 4 * c) * 4,
             &g_vt[(size_t)(b * H_SZ + r) * S_LEN + 4 * c]);
    }
    asm volatile("cp.async.commit_group;");

    // Q tile: plain vector loads
#pragma unroll
    for (int p = 0; p < 4; p++) {
        int f = p * 512 + tid;
        int r = f >> 4, c = f & 15;
        *reinterpret_cast<float4*>(&sm[QS_OFF + r * 68 + 4 * c]) =
            *reinterpret_cast<const float4*>(&g_q[(size_t)(b * S_LEN + q0 + r) * H_SZ + 4 * c]);
    }

    float m[4], l[4];
    u64 o2[4][4];
#pragma unroll
    for (int i = 0; i < 4; i++) {
        m[i] = -1e30f; l[i] = 0.f;
#pragma unroll
        for (int j = 0; j < 4; j++) o2[i][j] = 0ull;
    }

    for (int t = 0; t < S_LEN / 64; t++) {
        __syncthreads();                     // prev PV / P-buffer fully consumed
        if (t + 1 < S_LEN / 64) {
            const int buf = (t + 1) & 1;
            const int k0n = (t + 1) * 64;
#pragma unroll
            for (int p = 0; p < 2; p++) {
                int f = p * 512 + tid;
                int r = f >> 4, c = f & 15;
                cp16(smb + (KS_OFF + buf * BUF_STRIDE + r * 68 + 4 * c) * 4,
                     &g_k[(size_t)(b * S_LEN + k0n + r) * H_SZ + 4 * c]);
                cp16(smb + (VT_OFF + buf * BUF_STRIDE + r * 68 + 4 * c) * 4,
                     &g_vt[(size_t)(b * H_SZ + r) * S_LEN + k0n + 4 * c]);
            }
            asm volatile("cp.async.commit_group;");
            asm volatile("cp.async.wait_group 1;");
        } else {
            asm volatile("cp.async.wait_group 0;");
        }
        __syncthreads();                     // current K/V tile visible

        const float* Ks = sm + KS_OFF + (t & 1) * BUF_STRIDE;
        const float* Vt = sm + VT_OFF + (t & 1) * BUF_STRIDE;
        float* Pb = sm + PB_OFF;

        // ---- S = Q K^T : pack along h (same accumulation order as before)
        u64 acc[4][4];
#pragma unroll
        for (int i = 0; i < 4; i++)
#pragma unroll
            for (int j = 0; j < 4; j++) acc[i][j] = 0ull;

#pragma unroll 4
        for (int c = 0; c < 16; c++) {
            double2 qd[4], kd[4];
#pragma unroll
            for (int i = 0; i < 4; i++)
                qd[i] = *reinterpret_cast<const double2*>(&sm[QS_OFF + (4 * ty + i) * 68 + 4 * c]);
#pragma unroll
            for (int j = 0; j < 4; j++)
                kd[j] = *reinterpret_cast<const double2*>(&Ks[(tx + 16 * j) * 68 + 4 * c]);
#pragma unroll
            for (int i = 0; i < 4; i++)
#pragma unroll
                for (int j = 0; j < 4; j++) {
                    fma2(acc[i][j], qd[i].x, kd[j].x);
                    fma2(acc[i][j], qd[i].y, kd[j].y);
                }
        }

        // ---- floor + online softmax (row reduction over 16 tx lanes)
#pragma unroll
        for (int i = 0; i < 4; i++) {
            float s[4];
            float rm = -1e30f;
#pragma unroll
            for (int j = 0; j < 4; j++) {
                float2 f = unpack2(acc[i][j]);
                s[j] = floorf((f.x + f.y) * 0.125f);
                rm = fmaxf(rm, s[j]);
            }
#pragma unroll
            for (int d = 1; d < 16; d <<= 1)
                rm = fmaxf(rm, __shfl_xor_sync(0xffffffffu, rm, d));
            float mn = fmaxf(m[i], rm);
            float alpha = __expf(m[i] - mn);
            m[i] = mn;
            float pv[4];
            float rs = 0.f;
#pragma unroll
            for (int j = 0; j < 4; j++) {
                pv[j] = __expf(s[j] - mn);
                rs += pv[j];
            }
#pragma unroll
            for (int d = 1; d < 16; d <<= 1)
                rs += __shfl_xor_sync(0xffffffffu, rs, d);
            l[i] = l[i] * alpha + rs;
            u64 a2 = dup2(alpha);
#pragma unroll
            for (int j = 0; j < 4; j++) mul2(o2[i][j], a2);
#pragma unroll
            for (int j = 0; j < 4; j++)
                Pb[(4 * ty + i) * 68 + tx + 16 * j] = pv[j];
        }
        __syncthreads();                     // P tile complete

        // ---- O += P V : pack along k (same order as before)
#pragma unroll 4
        for (int c = 0; c < 16; c++) {
            double2 pd[4], vd[4];
#pragma unroll
            for (int i = 0; i < 4; i++)
                pd[i] = *reinterpret_cast<const double2*>(&Pb[(4 * ty + i) * 68 + 4 * c]);
#pragma unroll
            for (int j = 0; j < 4; j++)
                vd[j] = *reinterpret_cast<const double2*>(&Vt[(tx + 16 * j) * 68 + 4 * c]);
#pragma unroll
            for (int i = 0; i < 4; i++)
#pragma unroll
                for (int j = 0; j < 4; j++) {
                    fma2(o2[i][j], pd[i].x, vd[j].x);
                    fma2(o2[i][j], pd[i].y, vd[j].y);
                }
        }
    }

    // ---- epilogue
#pragma unroll
    for (int i = 0; i < 4; i++) {
        float inv = 1.0f / l[i];
#pragma unroll
        for (int j = 0; j < 4; j++) {
            float2 f = unpack2(o2[i][j]);
            out[(size_t)(b * S_LEN + q0 + 4 * ty + i) * H_SZ + tx + 16 * j] = (f.x + f.y) * inv;
        }
    }
}

// ---------------------------------------------------------------------------
extern "C" void kernel_launch(void* const* d_in, const int* in_sizes, int n_in,
                              void* d_out, int out_size)
{
    const float* x  = (const float*)d_in[0];
    const float* Wq = (const float*)d_in[1];
    const float* Wk = (const float*)d_in[2];
    const float* Wv = (const float*)d_in[3];
    float* out = (float*)d_out;

    cudaFuncSetAttribute(flash_kernel, cudaFuncAttributeMaxDynamicSharedMemorySize, SMEM_BYTES);

    qkv_kernel<<<dim3(128, 3), 256>>>(x, Wq, Wk, Wv);
    flash_kernel<<<dim3(S_LEN / 128, B_SZ), 512, SMEM_BYTES>>>(out);
}

// round 6
// speedup vs baseline: 1.7878x; 1.0951x over previous
#include <cuda_runtime.h>
#include <cstdint>
#include <math.h>

#define B_SZ 4
#define S_LEN 4096
#define E_SZ 768
#define H_SZ 64

typedef unsigned long long u64;

// Scratch: Q,K natural [b][s][h]; V transposed [b][h][s].
__device__ float g_q [B_SZ * S_LEN * H_SZ];
__device__ float g_k [B_SZ * S_LEN * H_SZ];
__device__ float g_vt[B_SZ * H_SZ * S_LEN];

// ---- packed fp32 helpers -------------------------------------------------
__device__ __forceinline__ void fma2(u64 &acc, double a, double b) {
    asm("fma.rn.f32x2 %0, %1, %2, %0;"
        : "+l"(acc)
        : "l"(__double_as_longlong(a)), "l"(__double_as_longlong(b)));
}
__device__ __forceinline__ float2 unpack2(u64 v) {
    float2 f; asm("mov.b64 {%0,%1}, %2;" : "=f"(f.x), "=f"(f.y) : "l"(v)); return f;
}
__device__ __forceinline__ void cp16(uint32_t dst, const float* src) {
    asm volatile("cp.async.cg.shared.global [%0], [%1], 16;" :: "r"(dst), "l"(src));
}

// ---------------------------------------------------------------------------
// Kernel 1: QKV projection. grid=(128,3), 256 thr.
// C[s][h] = sum_e x[s][e] W[h][e].  BM=128, BN=64, BK=32; tile 8x4; f32x2 on E.
// ---------------------------------------------------------------------------
__global__ __launch_bounds__(256, 2) void qkv_kernel(
    const float* __restrict__ x,
    const float* __restrict__ Wq,
    const float* __restrict__ Wk,
    const float* __restrict__ Wv)
{
    const int wsel = blockIdx.y;
    const float* __restrict__ W = (wsel == 0) ? Wq : (wsel == 1) ? Wk : Wv;

    __shared__ float xs[128 * 36];
    __shared__ float ws[64 * 36];

    const int tid = threadIdx.x;
    const int tx = tid & 15;
    const int ty = tid >> 4;
    const int rowBase = blockIdx.x * 128;

    u64 acc[8][4];
#pragma unroll
    for (int i = 0; i < 8; i++)
#pragma unroll
        for (int j = 0; j < 4; j++) acc[i][j] = 0ull;

    for (int kb = 0; kb < E_SZ; kb += 32) {
#pragma unroll
        for (int p = 0; p < 4; p++) {
            int f = p * 256 + tid;
            int r = f >> 3, c = f & 7;
            *reinterpret_cast<float4*>(&xs[r * 36 + 4 * c]) =
                *reinterpret_cast<const float4*>(&x[(size_t)(rowBase + r) * E_SZ + kb + 4 * c]);
        }
#pragma unroll
        for (int p = 0; p < 2; p++) {
            int f = p * 256 + tid;
            int r = f >> 3, c = f & 7;
            *reinterpret_cast<float4*>(&ws[r * 36 + 4 * c]) =
                *reinterpret_cast<const float4*>(&W[(size_t)r * E_SZ + kb + 4 * c]);
        }
        __syncthreads();
#pragma unroll 2
        for (int c = 0; c < 8; c++) {
            double2 xd[8], wd[4];
#pragma unroll
            for (int i = 0; i < 8; i++)
                xd[i] = *reinterpret_cast<const double2*>(&xs[(8 * ty + i) * 36 + 4 * c]);
#pragma unroll
            for (int j = 0; j < 4; j++)
                wd[j] = *reinterpret_cast<const double2*>(&ws[(tx + 16 * j) * 36 + 4 * c]);
#pragma unroll
            for (int i = 0; i < 8; i++)
#pragma unroll
                for (int j = 0; j < 4; j++) {
                    fma2(acc[i][j], xd[i].x, wd[j].x);
                    fma2(acc[i][j], xd[i].y, wd[j].y);
                }
        }
        __syncthreads();
    }

    float r_[8][4];
#pragma unroll
    for (int i = 0; i < 8; i++)
#pragma unroll
        for (int j = 0; j < 4; j++) {
            float2 f = unpack2(acc[i][j]);
            r_[i][j] = f.x + f.y;
        }

    const int b = rowBase >> 12;
    const int s0 = rowBase & 4095;
    if (wsel < 2) {
        float* dst = (wsel == 0) ? g_q : g_k;
#pragma unroll
        for (int i = 0; i < 8; i++)
#pragma unroll
            for (int j = 0; j < 4; j++)
                dst[(size_t)(b * S_LEN + s0 + 8 * ty + i) * H_SZ + tx + 16 * j] = r_[i][j];
    } else {
#pragma unroll
        for (int j = 0; j < 4; j++) {
            int h = tx + 16 * j;
            float* dst = &g_vt[(size_t)(b * H_SZ + h) * S_LEN + s0 + 8 * ty];
            *reinterpret_cast<float4*>(dst) = make_float4(r_[0][j], r_[1][j], r_[2][j], r_[3][j]);
            *reinterpret_cast<float4*>(dst + 4) = make_float4(r_[4][j], r_[5][j], r_[6][j], r_[7][j]);
        }
    }
}

// ---------------------------------------------------------------------------
// Kernel 2: flash attention. Scores are INTEGERS (floor(qk/8)) -> exp via
// smem lookup table, NO online max, NO rescale. O and l accumulate raw over
// all 64 k-tiles; single normalize at the end.
// grid=(32,4), 256 thr, 8x4 tile. f32x2-packed GEMMs. Double-buffered K/V.
// Smem (floats): Qs[128*68] | Ks[2][64*68] | Vt[2][64*68] | Pb[128*68].
// ---------------------------------------------------------------------------
#define QS_OFF 0
#define KS_OFF 8704
#define VT_OFF 17408
#define PB_OFF 26112
#define BUF_STRIDE 4352
#define SMEM_BYTES (34816 * 4)

__global__ __launch_bounds__(256, 1) void flash_kernel(float* __restrict__ out)
{
    extern __shared__ float sm[];
    __shared__ float tbl[256];           // tbl[i] = e^(i-124)

    const int tid = threadIdx.x;
    if (tid < 256) tbl[tid] = expf((float)(tid - 124));

    const int tx = tid & 15;     // k/h cols: tx + 16j
    const int ty = tid >> 4;     // q rows: 8ty + i
    const int b = blockIdx.y;
    const int q0 = blockIdx.x * 128;
    const uint32_t smb = (uint32_t)__cvta_generic_to_shared(sm);

    // prologue: async-load tile 0 (K & V)
#pragma unroll
    for (int p = 0; p < 4; p++) {
        int f = p * 256 + tid;
        int r = f >> 4, c = f & 15;
        cp16(smb + (KS_OFF + r * 68 + 4 * c) * 4,
             &g_k[(size_t)(b * S_LEN + r) * H_SZ + 4 * c]);
        cp16(smb + (VT_OFF + r * 68 + 4 * c) * 4,
             &g_vt[(size_t)(b * H_SZ + r) * S_LEN + 4 * c]);
    }
    asm volatile("cp.async.commit_group;");

    // Q tile
#pragma unroll
    for (int p = 0; p < 8; p++) {
        int f = p * 256 + tid;
        int r = f >> 4, c = f & 15;
        *reinterpret_cast<float4*>(&sm[QS_OFF + r * 68 + 4 * c]) =
            *reinterpret_cast<const float4*>(&g_q[(size_t)(b * S_LEN + q0 + r) * H_SZ + 4 * c]);
    }

    float l[8];
    u64 o2[8][4];
#pragma unroll
    for (int i = 0; i < 8; i++) {
        l[i] = 0.f;
#pragma unroll
        for (int j = 0; j < 4; j++) o2[i][j] = 0ull;
    }

    for (int t = 0; t < S_LEN / 64; t++) {
        __syncthreads();                 // prev P buffer fully consumed
        if (t + 1 < S_LEN / 64) {
            const int buf = (t + 1) & 1;
            const int k0n = (t + 1) * 64;
#pragma unroll
            for (int p = 0; p < 4; p++) {
                int f = p * 256 + tid;
                int r = f >> 4, c = f & 15;
                cp16(smb + (KS_OFF + buf * BUF_STRIDE + r * 68 + 4 * c) * 4,
                     &g_k[(size_t)(b * S_LEN + k0n + r) * H_SZ + 4 * c]);
                cp16(smb + (VT_OFF + buf * BUF_STRIDE + r * 68 + 4 * c) * 4,
                     &g_vt[(size_t)(b * H_SZ + r) * S_LEN + k0n + 4 * c]);
            }
            asm volatile("cp.async.commit_group;");
            asm volatile("cp.async.wait_group 1;");
        } else {
            asm volatile("cp.async.wait_group 0;");
        }
        __syncthreads();                 // current K/V tile visible

        const float* Ks = sm + KS_OFF + (t & 1) * BUF_STRIDE;
        const float* Vt = sm + VT_OFF + (t & 1) * BUF_STRIDE;
        float* Pb = sm + PB_OFF;

        // ---- S = Q K^T : f32x2 packed along h (same accumulation order)
        u64 acc[8][4];
#pragma unroll
        for (int i = 0; i < 8; i++)
#pragma unroll
            for (int j = 0; j < 4; j++) acc[i][j] = 0ull;

#pragma unroll 4
        for (int c = 0; c < 16; c++) {
            double2 qd[8], kd[4];
#pragma unroll
            for (int i = 0; i < 8; i++)
                qd[i] = *reinterpret_cast<const double2*>(&sm[QS_OFF + (8 * ty + i) * 68 + 4 * c]);
#pragma unroll
            for (int j = 0; j < 4; j++)
                kd[j] = *reinterpret_cast<const double2*>(&Ks[(tx + 16 * j) * 68 + 4 * c]);
#pragma unroll
            for (int i = 0; i < 8; i++)
#pragma unroll
                for (int j = 0; j < 4; j++) {
                    fma2(acc[i][j], qd[i].x, kd[j].x);
                    fma2(acc[i][j], qd[i].y, kd[j].y);
                }
        }

        // ---- integer scores -> exp via table; accumulate l; stage P
#pragma unroll
        for (int i = 0; i < 8; i++) {
            float pv[4];
#pragma unroll
            for (int j = 0; j < 4; j++) {
                float2 f = unpack2(acc[i][j]);
                int si = __float2int_rd((f.x + f.y) * 0.125f);
                si = si < -124 ? -124 : (si > 60 ? 60 : si);
                pv[j] = tbl[si + 124];
            }
            l[i] += (pv[0] + pv[1]) + (pv[2] + pv[3]);
#pragma unroll
            for (int j = 0; j < 4; j++)
                Pb[(8 * ty + i) * 68 + tx + 16 * j] = pv[j];
        }
        __syncthreads();                 // P tile complete

        // ---- O += P V : f32x2 packed along k
#pragma unroll 4
        for (int c = 0; c < 16; c++) {
            double2 pd[8], vd[4];
#pragma unroll
            for (int i = 0; i < 8; i++)
                pd[i] = *reinterpret_cast<const double2*>(&Pb[(8 * ty + i) * 68 + 4 * c]);
#pragma unroll
            for (int j = 0; j < 4; j++)
                vd[j] = *reinterpret_cast<const double2*>(&Vt[(tx + 16 * j) * 68 + 4 * c]);
#pragma unroll
            for (int i = 0; i < 8; i++)
#pragma unroll
                for (int j = 0; j < 4; j++) {
                    fma2(o2[i][j], pd[i].x, vd[j].x);
                    fma2(o2[i][j], pd[i].y, vd[j].y);
                }
        }
    }

    // ---- epilogue: single row-sum reduction over the 16 tx lanes, normalize
#pragma unroll
    for (int i = 0; i < 8; i++) {
        float rs = l[i];
#pragma unroll
        for (int d = 1; d < 16; d <<= 1)
            rs += __shfl_xor_sync(0xffffffffu, rs, d);
        float inv = 1.0f / rs;
#pragma unroll
        for (int j = 0; j < 4; j++) {
            float2 f = unpack2(o2[i][j]);
            out[(size_t)(b * S_LEN + q0 + 8 * ty + i) * H_SZ + tx + 16 * j] = (f.x + f.y) * inv;
        }
    }
}

// ---------------------------------------------------------------------------
extern "C" void kernel_launch(void* const* d_in, const int* in_sizes, int n_in,
                              void* d_out, int out_size)
{
    const float* x  = (const float*)d_in[0];
    const float* Wq = (const float*)d_in[1];
    const float* Wk = (const float*)d_in[2];
    const float* Wv = (const float*)d_in[3];
    float* out = (float*)d_out;

    cudaFuncSetAttribute(flash_kernel, cudaFuncAttributeMaxDynamicSharedMemorySize, SMEM_BYTES);

    qkv_kernel<<<dim3(128, 3), 256>>>(x, Wq, Wk, Wv);
    flash_kernel<<<dim3(S_LEN / 128, B_SZ), 256, SMEM_BYTES>>>(out);
}

// round 8
// speedup vs baseline: 3.0928x; 1.7300x over previous
#include <cuda_runtime.h>
#include <cuda_bf16.h>
#include <cstdint>
#include <math.h>

#define B_SZ 4
#define S_LEN 4096
#define E_SZ 768
#define H_SZ 64

typedef unsigned long long u64;

// bf16 splits, all [b,s,64] row-major. Q pre-scaled by 1/8.
__device__ __nv_bfloat16 g_qh[B_SZ * S_LEN * H_SZ];
__device__ __nv_bfloat16 g_qm[B_SZ * S_LEN * H_SZ];
__device__ __nv_bfloat16 g_ql[B_SZ * S_LEN * H_SZ];
__device__ __nv_bfloat16 g_kh[B_SZ * S_LEN * H_SZ];
__device__ __nv_bfloat16 g_km[B_SZ * S_LEN * H_SZ];
__device__ __nv_bfloat16 g_kl[B_SZ * S_LEN * H_SZ];
__device__ __nv_bfloat16 g_vh[B_SZ * S_LEN * H_SZ];
__device__ __nv_bfloat16 g_vl[B_SZ * S_LEN * H_SZ];

// ---- helpers ---------------------------------------------------------------
__device__ __forceinline__ void fma2(u64 &acc, double a, double b) {
    asm("fma.rn.f32x2 %0, %1, %2, %0;"
        : "+l"(acc)
        : "l"(__double_as_longlong(a)), "l"(__double_as_longlong(b)));
}
__device__ __forceinline__ float2 unpack2(u64 v) {
    float2 f; asm("mov.b64 {%0,%1}, %2;" : "=f"(f.x), "=f"(f.y) : "l"(v)); return f;
}
__device__ __forceinline__ void cp16(uint32_t dst, const void* src) {
    asm volatile("cp.async.cg.shared.global [%0], [%1], 16;" :: "r"(dst), "l"(src));
}
__device__ __forceinline__ uint32_t smem_u32(const void* p) {
    uint32_t a;
    asm("{ .reg .u64 t; cvta.to.shared.u64 t, %1; cvt.u32.u64 %0, t; }" : "=r"(a) : "l"(p));
    return a;
}
__device__ __forceinline__ uint32_t pack_bf16(float lo, float hi) {
    uint32_t r;
    asm("cvt.rn.satfinite.bf16x2.f32 %0, %1, %2;" : "=r"(r) : "f"(hi), "f"(lo));
    return r;
}
__device__ __forceinline__ float bf16lo_f(uint32_t w) {
    float f;
    asm("{ .reg .b16 l, h; mov.b32 {l, h}, %1; cvt.f32.bf16 %0, l; }" : "=f"(f) : "r"(w));
    return f;
}
__device__ __forceinline__ float bf16hi_f(uint32_t w) {
    float f;
    asm("{ .reg .b16 l, h; mov.b32 {l, h}, %1; cvt.f32.bf16 %0, h; }" : "=f"(f) : "r"(w));
    return f;
}
#define SWZ(o) ((uint32_t)(o) ^ ((((uint32_t)(o)) >> 3) & 0x70))
#define CP_COMMIT() asm volatile("cp.async.commit_group;" ::: "memory")
#define CP_WAIT0()  asm volatile("cp.async.wait_group 0;" ::: "memory")

__device__ __forceinline__ void ldsm4(uint32_t a, uint32_t* r) {
    asm volatile("ldmatrix.sync.aligned.m8n8.x4.shared.b16 {%0,%1,%2,%3}, [%4];"
                 : "=r"(r[0]), "=r"(r[1]), "=r"(r[2]), "=r"(r[3]) : "r"(a));
}
__device__ __forceinline__ void ldsm4t(uint32_t a, uint32_t* r) {
    asm volatile("ldmatrix.sync.aligned.m8n8.x4.trans.shared.b16 {%0,%1,%2,%3}, [%4];"
                 : "=r"(r[0]), "=r"(r[1]), "=r"(r[2]), "=r"(r[3]) : "r"(a));
}
__device__ __forceinline__ void mma16816(float* c, const uint32_t* a, const uint32_t* b) {
    asm volatile(
        "mma.sync.aligned.m16n8k16.row.col.f32.bf16.bf16.f32 "
        "{%0,%1,%2,%3}, {%4,%5,%6,%7}, {%8,%9}, {%0,%1,%2,%3};"
        : "+f"(c[0]), "+f"(c[1]), "+f"(c[2]), "+f"(c[3])
        : "r"(a[0]), "r"(a[1]), "r"(a[2]), "r"(a[3]), "r"(b[0]), "r"(b[1]));
}

// ---------------------------------------------------------------------------
// Kernel 1: QKV projection (fp32 FFMA2 GEMM) + bf16-split epilogue.
// grid=(128,3), 256 thr. wsel 0=Q (x1/8, 3 splits), 1=K (3), 2=V (2).
// ---------------------------------------------------------------------------
__global__ __launch_bounds__(256, 2) void qkv_kernel(
    const float* __restrict__ x,
    const float* __restrict__ Wq,
    const float* __restrict__ Wk,
    const float* __restrict__ Wv)
{
    const int wsel = blockIdx.y;
    const float* __restrict__ W = (wsel == 0) ? Wq : (wsel == 1) ? Wk : Wv;

    __shared__ float xs[128 * 36];
    __shared__ float ws[64 * 36];

    const int tid = threadIdx.x;
    const int tx = tid & 15;
    const int ty = tid >> 4;
    const int rowBase = blockIdx.x * 128;

    u64 acc[8][4];
#pragma unroll
    for (int i = 0; i < 8; i++)
#pragma unroll
        for (int j = 0; j < 4; j++) acc[i][j] = 0ull;

    for (int kb = 0; kb < E_SZ; kb += 32) {
#pragma unroll
        for (int p = 0; p < 4; p++) {
            int f = p * 256 + tid;
            int r = f >> 3, c = f & 7;
            *reinterpret_cast<float4*>(&xs[r * 36 + 4 * c]) =
                *reinterpret_cast<const float4*>(&x[(size_t)(rowBase + r) * E_SZ + kb + 4 * c]);
        }
#pragma unroll
        for (int p = 0; p < 2; p++) {
            int f = p * 256 + tid;
            int r = f >> 3, c = f & 7;
            *reinterpret_cast<float4*>(&ws[r * 36 + 4 * c]) =
                *reinterpret_cast<const float4*>(&W[(size_t)r * E_SZ + kb + 4 * c]);
        }
        __syncthreads();
#pragma unroll 2
        for (int c = 0; c < 8; c++) {
            double2 xd[8], wd[4];
#pragma unroll
            for (int i = 0; i < 8; i++)
                xd[i] = *reinterpret_cast<const double2*>(&xs[(8 * ty + i) * 36 + 4 * c]);
#pragma unroll
            for (int j = 0; j < 4; j++)
                wd[j] = *reinterpret_cast<const double2*>(&ws[(tx + 16 * j) * 36 + 4 * c]);
#pragma unroll
            for (int i = 0; i < 8; i++)
#pragma unroll
                for (int j = 0; j < 4; j++) {
                    fma2(acc[i][j], xd[i].x, wd[j].x);
                    fma2(acc[i][j], xd[i].y, wd[j].y);
                }
        }
        __syncthreads();
    }

    const int b = rowBase >> 12;
    const int s0 = rowBase & 4095;

#pragma unroll
    for (int i = 0; i < 8; i++)
#pragma unroll
        for (int j = 0; j < 4; j++) {
            float2 f2 = unpack2(acc[i][j]);
            float v = f2.x + f2.y;
            size_t idx = (size_t)(b * S_LEN + s0 + 8 * ty + i) * H_SZ + tx + 16 * j;
            if (wsel == 0) {
                v *= 0.125f;
                __nv_bfloat16 h = __float2bfloat16(v);
                float r1 = v - __bfloat162float(h);
                __nv_bfloat16 m_ = __float2bfloat16(r1);
                g_qh[idx] = h; g_qm[idx] = m_;
                g_ql[idx] = __float2bfloat16(r1 - __bfloat162float(m_));
            } else if (wsel == 1) {
                __nv_bfloat16 h = __float2bfloat16(v);
                float r1 = v - __bfloat162float(h);
                __nv_bfloat16 m_ = __float2bfloat16(r1);
                g_kh[idx] = h; g_km[idx] = m_;
                g_kl[idx] = __float2bfloat16(r1 - __bfloat162float(m_));
            } else {
                __nv_bfloat16 h = __float2bfloat16(v);
                g_vh[idx] = h;
                g_vl[idx] = __float2bfloat16(v - __bfloat162float(h));
            }
        }
}

// ---------------------------------------------------------------------------
// Kernel 2: flash attention on mma.sync (HMMA bf16), grid (32,4), 256 thr.
// Per warp: 16 q-rows. S via 6 split-MMAs; exp via smem table; P packed from
// accumulators into A frags (2-way split); PV via 3 split-MMAs; O in regs.
// Smem: tbl 1KB | Q 3x16KB | K 3x(2x8KB) | V 2x(2x8KB) = 132096 B.
// ---------------------------------------------------------------------------
#define TBL_OFF 0
#define Q_OFF   1024
#define K_OFF   50176
#define V_OFF   99328
#define FL_SMEM 132096

__device__ __forceinline__ void load_kv(uint32_t smb, int b, int kt, int buf, int tid) {
    const int k0 = kt * 64;
    const __nv_bfloat16* ks[3] = {g_kh, g_km, g_kl};
    const __nv_bfloat16* vs[2] = {g_vh, g_vl};
#pragma unroll
    for (int s = 0; s < 3; s++)
#pragma unroll
        for (int p = 0; p < 2; p++) {
            int idx = p * 256 + tid;
            int r = idx >> 3, c = idx & 7;
            cp16(smb + K_OFF + s * 16384 + buf * 8192 + SWZ(r * 128 + c * 16),
                 ks[s] + (size_t)(b * S_LEN + k0 + r) * H_SZ + c * 8);
        }
#pragma unroll
    for (int s = 0; s < 2; s++)
#pragma unroll
        for (int p = 0; p < 2; p++) {
            int idx = p * 256 + tid;
            int r = idx >> 3, c = idx & 7;
            cp16(smb + V_OFF + s * 16384 + buf * 8192 + SWZ(r * 128 + c * 16),
                 vs[s] + (size_t)(b * S_LEN + k0 + r) * H_SZ + c * 8);
        }
}

__global__ __launch_bounds__(256, 1) void flash_kernel(float* __restrict__ out)
{
    extern __shared__ char smc[];
    float* tbl = (float*)(smc + TBL_OFF);
    const uint32_t smb = smem_u32(smc);

    const int tid = threadIdx.x;
    const int lane = tid & 31;
    const int wid = tid >> 5;
    const int b = blockIdx.y;
    const int q0 = blockIdx.x * 128;
    const int qrow0 = wid * 16;

    tbl[tid] = expf((float)(tid - 124));   // tbl[i] = e^(i-124)

    // ---- prologue: Q splits + KV tile 0 via cp.async
    {
        const __nv_bfloat16* qs[3] = {g_qh, g_qm, g_ql};
#pragma unroll
        for (int s = 0; s < 3; s++)
#pragma unroll
            for (int p = 0; p < 4; p++) {
                int idx = p * 256 + tid;
                int r = idx >> 3, c = idx & 7;
                cp16(smb + Q_OFF + s * 16384 + SWZ(r * 128 + c * 16),
                     qs[s] + (size_t)(b * S_LEN + q0 + r) * H_SZ + c * 8);
            }
    }
    load_kv(smb, b, 0, 0, tid);
    CP_COMMIT();
    CP_WAIT0();
    __syncthreads();

    const int mat = lane >> 3, rin = lane & 7;

    // ---- Q fragments (persistent): qa[split][kc][4]
    uint32_t qa[3][4][4];
#pragma unroll
    for (int s = 0; s < 3; s++)
#pragma unroll
        for (int kc = 0; kc < 4; kc++) {
            uint32_t a = smb + Q_OFF + s * 16384 +
                SWZ((qrow0 + ((mat & 1) << 3) + rin) * 128 + 32 * kc + ((mat >> 1) << 4));
            ldsm4(a, qa[s][kc]);
        }

    float co[8][4];
#pragma unroll
    for (int j = 0; j < 8; j++)
#pragma unroll
        for (int r = 0; r < 4; r++) co[j][r] = 0.f;
    float lsA = 0.f, lsB = 0.f;

    for (int t = 0; t < S_LEN / 64; t++) {
        if (t > 0) { CP_WAIT0(); __syncthreads(); }
        if (t + 1 < S_LEN / 64) { load_kv(smb, b, t + 1, (t + 1) & 1, tid); CP_COMMIT(); }

        const uint32_t kbase = smb + K_OFF + (t & 1) * 8192;
        const uint32_t vbase = smb + V_OFF + (t & 1) * 8192;

        // ---- S = (Q/8)·K^T via 6 split terms
        float sc[8][4];
#pragma unroll
        for (int j = 0; j < 8; j++)
#pragma unroll
            for (int r = 0; r < 4; r++) sc[j][r] = 0.f;

#pragma unroll
        for (int kc = 0; kc < 4; kc++) {
            uint32_t kb[3][4][4];
#pragma unroll
            for (int s = 0; s < 3; s++)
#pragma unroll
                for (int jj = 0; jj < 4; jj++) {
                    uint32_t a = kbase + s * 16384 +
                        SWZ((16 * jj + ((mat >> 1) << 3) + rin) * 128 + 32 * kc + ((mat & 1) << 4));
                    ldsm4(a, kb[s][jj]);
                }
            const int pa[6] = {0, 0, 1, 1, 0, 2};
            const int pb[6] = {0, 1, 0, 1, 2, 0};
#pragma unroll
            for (int p = 0; p < 6; p++)
#pragma unroll
                for (int j = 0; j < 8; j++)
                    mma16816(sc[j], qa[pa[p]][kc], &kb[pb[p]][j >> 1][(j & 1) * 2]);
        }

        // ---- integer scores -> table exp; pack P (2-way split) into A frags
        uint32_t ph[4][4], pl[4][4];
#pragma unroll
        for (int j = 0; j < 8; j++) {
            int s0 = __float2int_rd(sc[j][0]); s0 = max(-124, min(60, s0));
            int s1 = __float2int_rd(sc[j][1]); s1 = max(-124, min(60, s1));
            int s2 = __float2int_rd(sc[j][2]); s2 = max(-124, min(60, s2));
            int s3 = __float2int_rd(sc[j][3]); s3 = max(-124, min(60, s3));
            float p0 = tbl[s0 + 124], p1 = tbl[s1 + 124];
            float p2 = tbl[s2 + 124], p3 = tbl[s3 + 124];
            lsA += p0 + p1;
            lsB += p2 + p3;
            int u = j >> 1, h2 = (j & 1) * 2;
            uint32_t w0 = pack_bf16(p0, p1), w1 = pack_bf16(p2, p3);
            ph[u][h2]     = w0;
            ph[u][h2 + 1] = w1;
            pl[u][h2]     = pack_bf16(p0 - bf16lo_f(w0), p1 - bf16hi_f(w0));
            pl[u][h2 + 1] = pack_bf16(p2 - bf16lo_f(w1), p3 - bf16hi_f(w1));
        }

        // ---- O += P·V via 3 split terms (V loaded with ldmatrix.trans)
#pragma unroll
        for (int u = 0; u < 4; u++) {
            uint32_t vb[2][4][4];
#pragma unroll
            for (int s = 0; s < 2; s++)
#pragma unroll
                for (int jj = 0; jj < 4; jj++) {
                    uint32_t a = vbase + s * 16384 +
                        SWZ((16 * u + ((mat & 1) << 3) + rin) * 128 + 32 * jj + ((mat >> 1) << 4));
                    ldsm4t(a, vb[s][jj]);
                }
#pragma unroll
            for (int j = 0; j < 8; j++) {
                mma16816(co[j], ph[u], &vb[0][j >> 1][(j & 1) * 2]);
                mma16816(co[j], ph[u], &vb[1][j >> 1][(j & 1) * 2]);
                mma16816(co[j], pl[u], &vb[0][j >> 1][(j & 1) * 2]);
            }
        }
    }

    // ---- epilogue: quad-reduce row sums, normalize, store
#pragma unroll
    for (int d = 1; d < 4; d <<= 1) {
        lsA += __shfl_xor_sync(0xffffffffu, lsA, d);
        lsB += __shfl_xor_sync(0xffffffffu, lsB, d);
    }
    const float invA = 1.0f / lsA;
    const float invB = 1.0f / lsB;

    const int g = lane >> 2, tq = lane & 3;
    float* oA = out + (size_t)(b * S_LEN + q0 + qrow0 + g) * H_SZ;
    float* oB = out + (size_t)(b * S_LEN + q0 + qrow0 + g + 8) * H_SZ;
#pragma unroll
    for (int j = 0; j < 8; j++) {
        int cb = 8 * j + 2 * tq;
        *reinterpret_cast<float2*>(oA + cb) = make_float2(co[j][0] * invA, co[j][1] * invA);
        *reinterpret_cast<float2*>(oB + cb) = make_float2(co[j][2] * invB, co[j][3] * invB);
    }
}

// ---------------------------------------------------------------------------
extern "C" void kernel_launch(void* const* d_in, const int* in_sizes, int n_in,
                              void* d_out, int out_size)
{
    const float* x  = (const float*)d_in[0];
    const float* Wq = (const float*)d_in[1];
    const float* Wk = (const float*)d_in[2];
    const float* Wv = (const float*)d_in[3];
    float* out = (float*)d_out;

    cudaFuncSetAttribute(flash_kernel, cudaFuncAttributeMaxDynamicSharedMemorySize, FL_SMEM);

    qkv_kernel<<<dim3(128, 3), 256>>>(x, Wq, Wk, Wv);
    flash_kernel<<<dim3(S_LEN / 128, B_SZ), 256, FL_SMEM>>>(out);
}

// round 10
// speedup vs baseline: 3.6144x; 1.1687x over previous
#include <cuda_runtime.h>
#include <cuda_bf16.h>
#include <cstdint>
#include <math.h>

#define B_SZ 4
#define S_LEN 4096
#define E_SZ 768
#define H_SZ 64
#define NROW (B_SZ * S_LEN)

// x splits [b,s,768]; W splits [3][64,768]; Q/K 3-way, V 2-way splits [b,s,64].
__device__ __nv_bfloat16 g_xh[NROW * E_SZ];
__device__ __nv_bfloat16 g_xm[NROW * E_SZ];
__device__ __nv_bfloat16 g_xl[NROW * E_SZ];
__device__ __nv_bfloat16 g_wh[3 * H_SZ * E_SZ];
__device__ __nv_bfloat16 g_wm[3 * H_SZ * E_SZ];
__device__ __nv_bfloat16 g_wl[3 * H_SZ * E_SZ];
__device__ __nv_bfloat16 g_qh[NROW * H_SZ];
__device__ __nv_bfloat16 g_qm[NROW * H_SZ];
__device__ __nv_bfloat16 g_ql[NROW * H_SZ];
__device__ __nv_bfloat16 g_kh[NROW * H_SZ];
__device__ __nv_bfloat16 g_km[NROW * H_SZ];
__device__ __nv_bfloat16 g_kl[NROW * H_SZ];
__device__ __nv_bfloat16 g_vh[NROW * H_SZ];
__device__ __nv_bfloat16 g_vl[NROW * H_SZ];

// ---- helpers ---------------------------------------------------------------
__device__ __forceinline__ void cp16(uint32_t dst, const void* src) {
    asm volatile("cp.async.cg.shared.global [%0], [%1], 16;" :: "r"(dst), "l"(src));
}
__device__ __forceinline__ uint32_t smem_u32(const void* p) {
    uint32_t a;
    asm("{ .reg .u64 t; cvta.to.shared.u64 t, %1; cvt.u32.u64 %0, t; }" : "=r"(a) : "l"(p));
    return a;
}
__device__ __forceinline__ uint32_t pack_bf16(float lo, float hi) {
    uint32_t r;
    asm("cvt.rn.satfinite.bf16x2.f32 %0, %1, %2;" : "=r"(r) : "f"(hi), "f"(lo));
    return r;
}
__device__ __forceinline__ float bf16lo_f(uint32_t w) {
    float f;
    asm("{ .reg .b16 l, h; mov.b32 {l, h}, %1; cvt.f32.bf16 %0, l; }" : "=f"(f) : "r"(w));
    return f;
}
__device__ __forceinline__ float bf16hi_f(uint32_t w) {
    float f;
    asm("{ .reg .b16 l, h; mov.b32 {l, h}, %1; cvt.f32.bf16 %0, h; }" : "=f"(f) : "r"(w));
    return f;
}
#define SWZ(o) ((uint32_t)(o) ^ ((((uint32_t)(o)) >> 3) & 0x70))
#define CP_COMMIT() asm volatile("cp.async.commit_group;" ::: "memory")
#define CP_WAIT0()  asm volatile("cp.async.wait_group 0;" ::: "memory")

__device__ __forceinline__ void ldsm4(uint32_t a, uint32_t* r) {
    asm volatile("ldmatrix.sync.aligned.m8n8.x4.shared.b16 {%0,%1,%2,%3}, [%4];"
                 : "=r"(r[0]), "=r"(r[1]), "=r"(r[2]), "=r"(r[3]) : "r"(a));
}
__device__ __forceinline__ void ldsm4t(uint32_t a, uint32_t* r) {
    asm volatile("ldmatrix.sync.aligned.m8n8.x4.trans.shared.b16 {%0,%1,%2,%3}, [%4];"
                 : "=r"(r[0]), "=r"(r[1]), "=r"(r[2]), "=r"(r[3]) : "r"(a));
}
__device__ __forceinline__ void mma16816(float* c, const uint32_t* a, const uint32_t* b) {
    asm volatile(
        "mma.sync.aligned.m16n8k16.row.col.f32.bf16.bf16.f32 "
        "{%0,%1,%2,%3}, {%4,%5,%6,%7}, {%8,%9}, {%0,%1,%2,%3};"
        : "+f"(c[0]), "+f"(c[1]), "+f"(c[2]), "+f"(c[3])
        : "r"(a[0]), "r"(a[1]), "r"(a[2]), "r"(a[3]), "r"(b[0]), "r"(b[1]));
}

// ---------------------------------------------------------------------------
// Kernel 0: prep — split x and W into bf16 components.
// ---------------------------------------------------------------------------
#define XBLK 12288

__global__ __launch_bounds__(256) void prep_kernel(
    const float* __restrict__ x,
    const float* __restrict__ Wq,
    const float* __restrict__ Wk,
    const float* __restrict__ Wv)
{
    const int tid = threadIdx.x;
    if (blockIdx.x < XBLK) {
        size_t i4 = ((size_t)blockIdx.x * 256 + tid) * 4;
        float4 v = *reinterpret_cast<const float4*>(x + i4);
        float f[4] = {v.x, v.y, v.z, v.w};
        uint32_t h[2], m[2], l[2];
#pragma unroll
        for (int p = 0; p < 2; p++) {
            float a = f[2 * p], c = f[2 * p + 1];
            h[p] = pack_bf16(a, c);
            float ra = a - bf16lo_f(h[p]), rc = c - bf16hi_f(h[p]);
            m[p] = pack_bf16(ra, rc);
            l[p] = pack_bf16(ra - bf16lo_f(m[p]), rc - bf16hi_f(m[p]));
        }
        *reinterpret_cast<uint2*>(&g_xh[i4]) = make_uint2(h[0], h[1]);
        *reinterpret_cast<uint2*>(&g_xm[i4]) = make_uint2(m[0], m[1]);
        *reinterpret_cast<uint2*>(&g_xl[i4]) = make_uint2(l[0], l[1]);
    } else {
        size_t i4 = ((size_t)(blockIdx.x - XBLK) * 256 + tid) * 4;   // [0, 147456)
        int wsel = (int)(i4 / (H_SZ * E_SZ));
        size_t off = i4 % (H_SZ * E_SZ);
        const float* W = (wsel == 0) ? Wq : (wsel == 1) ? Wk : Wv;
        float4 v = *reinterpret_cast<const float4*>(W + off);
        float f[4] = {v.x, v.y, v.z, v.w};
        uint32_t h[2], m[2], l[2];
#pragma unroll
        for (int p = 0; p < 2; p++) {
            float a = f[2 * p], c = f[2 * p + 1];
            h[p] = pack_bf16(a, c);
            float ra = a - bf16lo_f(h[p]), rc = c - bf16hi_f(h[p]);
            m[p] = pack_bf16(ra, rc);
            l[p] = pack_bf16(ra - bf16lo_f(m[p]), rc - bf16hi_f(m[p]));
        }
        *reinterpret_cast<uint2*>(&g_wh[i4]) = make_uint2(h[0], h[1]);
        *reinterpret_cast<uint2*>(&g_wm[i4]) = make_uint2(m[0], m[1]);
        *reinterpret_cast<uint2*>(&g_wl[i4]) = make_uint2(l[0], l[1]);
    }
}

// ---------------------------------------------------------------------------
// Kernel 1: QKV projection on mma.sync, 6-term bf16 split, SPLIT ACCUMULATORS:
// coH accumulates hh only; coC accumulates the 5 small correction terms.
// Final q/k error ~= scalar fp32 path (restores R8 floor-flip rate).
// grid=(128,3), 256 thr.
// ---------------------------------------------------------------------------
#define XS_OFF 0
#define WS_OFF 98304
#define QKV_SMEM 147456

__global__ __launch_bounds__(256, 1) void qkv_mma_kernel()
{
    extern __shared__ char smc[];
    const uint32_t smb = smem_u32(smc);
    const int tid = threadIdx.x;
    const int lane = tid & 31;
    const int wid = tid >> 5;
    const int wsel = blockIdx.y;
    const int rowBase = blockIdx.x * 128;
    const int qrow0 = wid * 16;
    const int mat = lane >> 3, rin = lane & 7;

    const __nv_bfloat16* xsrc[3] = {g_xh, g_xm, g_xl};
    const __nv_bfloat16* wsrc[3] = {g_wh, g_wm, g_wl};
    const size_t woff = (size_t)wsel * H_SZ * E_SZ;

    auto load_tiles = [&](int kt, int buf) {
        const int e0 = kt * 64;
#pragma unroll
        for (int s = 0; s < 3; s++) {
#pragma unroll
            for (int p = 0; p < 4; p++) {
                int idx = p * 256 + tid;
                int r = idx >> 3, c = idx & 7;
                cp16(smb + XS_OFF + s * 32768 + buf * 16384 + SWZ(r * 128 + c * 16),
                     xsrc[s] + (size_t)(rowBase + r) * E_SZ + e0 + c * 8);
            }
#pragma unroll
            for (int p = 0; p < 2; p++) {
                int idx = p * 256 + tid;
                int r = idx >> 3, c = idx & 7;
                cp16(smb + WS_OFF + s * 16384 + buf * 8192 + SWZ(r * 128 + c * 16),
                     wsrc[s] + woff + (size_t)r * E_SZ + e0 + c * 8);
            }
        }
    };

    load_tiles(0, 0);
    CP_COMMIT();
    CP_WAIT0();
    __syncthreads();

    float coH[8][4], coC[8][4];
#pragma unroll
    for (int j = 0; j < 8; j++)
#pragma unroll
        for (int r = 0; r < 4; r++) { coH[j][r] = 0.f; coC[j][r] = 0.f; }

    // correction terms (exclude hh which goes to coH)
    const int ca[5] = {0, 1, 1, 0, 2};
    const int cb[5] = {1, 0, 1, 2, 0};

    for (int t = 0; t < E_SZ / 64; t++) {
        if (t > 0) { CP_WAIT0(); __syncthreads(); }
        if (t + 1 < E_SZ / 64) { load_tiles(t + 1, (t + 1) & 1); CP_COMMIT(); }

        const uint32_t xb = smb + XS_OFF + (t & 1) * 16384;
        const uint32_t wb = smb + WS_OFF + (t & 1) * 8192;

#pragma unroll
        for (int kc = 0; kc < 4; kc++) {
            uint32_t av[3][4];
#pragma unroll
            for (int s = 0; s < 3; s++)
                ldsm4(xb + s * 32768 +
                      SWZ((qrow0 + ((mat & 1) << 3) + rin) * 128 + 32 * kc + ((mat >> 1) << 4)),
                      av[s]);
            uint32_t bv[3][4][4];
#pragma unroll
            for (int s = 0; s < 3; s++)
#pragma unroll
                for (int jj = 0; jj < 4; jj++)
                    ldsm4(wb + s * 16384 +
                          SWZ((16 * jj + ((mat >> 1) << 3) + rin) * 128 + 32 * kc + ((mat & 1) << 4)),
                          bv[s][jj]);
            // hh -> coH (big term, clean accumulation)
#pragma unroll
            for (int j = 0; j < 8; j++)
                mma16816(coH[j], av[0], &bv[0][j >> 1][(j & 1) * 2]);
            // corrections -> coC
#pragma unroll
            for (int p = 0; p < 5; p++)
#pragma unroll
                for (int j = 0; j < 8; j++)
                    mma16816(coC[j], av[ca[p]], &bv[cb[p]][j >> 1][(j & 1) * 2]);
        }
    }

    // ---- epilogue: co = coH + coC, split to bf16 components, paired stores
    const int g = lane >> 2, tq = lane & 3;
    const float scale = (wsel == 0) ? 0.125f : 1.0f;
#pragma unroll
    for (int j = 0; j < 8; j++) {
#pragma unroll
        for (int half = 0; half < 2; half++) {
            int row = rowBase + qrow0 + g + 8 * half;
            int col = 8 * j + 2 * tq;
            float v0 = (coH[j][2 * half]     + coC[j][2 * half])     * scale;
            float v1 = (coH[j][2 * half + 1] + coC[j][2 * half + 1]) * scale;
            uint32_t uh = pack_bf16(v0, v1);
            float r0 = v0 - bf16lo_f(uh), r1 = v1 - bf16hi_f(uh);
            uint32_t um = pack_bf16(r0, r1);
            size_t boff = ((size_t)row * H_SZ + col) * 2;
            if (wsel == 0) {
                *(uint32_t*)((char*)g_qh + boff) = uh;
                *(uint32_t*)((char*)g_qm + boff) = um;
                *(uint32_t*)((char*)g_ql + boff) =
                    pack_bf16(r0 - bf16lo_f(um), r1 - bf16hi_f(um));
            } else if (wsel == 1) {
                *(uint32_t*)((char*)g_kh + boff) = uh;
                *(uint32_t*)((char*)g_km + boff) = um;
                *(uint32_t*)((char*)g_kl + boff) =
                    pack_bf16(r0 - bf16lo_f(um), r1 - bf16hi_f(um));
            } else {
                *(uint32_t*)((char*)g_vh + boff) = uh;
                *(uint32_t*)((char*)g_vl + boff) = um;
            }
        }
    }
}

// ---------------------------------------------------------------------------
// Kernel 2: flash attention on mma.sync (unchanged from R8, proven 192us).
// ---------------------------------------------------------------------------
#define TBL_OFF 0
#define Q_OFF   1024
#define K_OFF   50176
#define V_OFF   99328
#define FL_SMEM 132096

__device__ __forceinline__ void load_kv(uint32_t smb, int b, int kt, int buf, int tid) {
    const int k0 = kt * 64;
    const __nv_bfloat16* ks[3] = {g_kh, g_km, g_kl};
    const __nv_bfloat16* vs[2] = {g_vh, g_vl};
#pragma unroll
    for (int s = 0; s < 3; s++)
#pragma unroll
        for (int p = 0; p < 2; p++) {
            int idx = p * 256 + tid;
            int r = idx >> 3, c = idx & 7;
            cp16(smb + K_OFF + s * 16384 + buf * 8192 + SWZ(r * 128 + c * 16),
                 ks[s] + (size_t)(b * S_LEN + k0 + r) * H_SZ + c * 8);
        }
#pragma unroll
    for (int s = 0; s < 2; s++)
#pragma unroll
        for (int p = 0; p < 2; p++) {
            int idx = p * 256 + tid;
            int r = idx >> 3, c = idx & 7;
            cp16(smb + V_OFF + s * 16384 + buf * 8192 + SWZ(r * 128 + c * 16),
                 vs[s] + (size_t)(b * S_LEN + k0 + r) * H_SZ + c * 8);
        }
}

__global__ __launch_bounds__(256, 1) void flash_kernel(float* __restrict__ out)
{
    extern __shared__ char smc[];
    float* tbl = (float*)(smc + TBL_OFF);
    const uint32_t smb = smem_u32(smc);

    const int tid = threadIdx.x;
    const int lane = tid & 31;
    const int wid = tid >> 5;
    const int b = blockIdx.y;
    const int q0 = blockIdx.x * 128;
    const int qrow0 = wid * 16;

    tbl[tid] = expf((float)(tid - 124));

    {
        const __nv_bfloat16* qs[3] = {g_qh, g_qm, g_ql};
#pragma unroll
        for (int s = 0; s < 3; s++)
#pragma unroll
            for (int p = 0; p < 4; p++) {
                int idx = p * 256 + tid;
                int r = idx >> 3, c = idx & 7;
                cp16(smb + Q_OFF + s * 16384 + SWZ(r * 128 + c * 16),
                     qs[s] + (size_t)(b * S_LEN + q0 + r) * H_SZ + c * 8);
            }
    }
    load_kv(smb, b, 0, 0, tid);
    CP_COMMIT();
    CP_WAIT0();
    __syncthreads();

    const int mat = lane >> 3, rin = lane & 7;

    uint32_t qa[3][4][4];
#pragma unroll
    for (int s = 0; s < 3; s++)
#pragma unroll
        for (int kc = 0; kc < 4; kc++) {
            uint32_t a = smb + Q_OFF + s * 16384 +
                SWZ((qrow0 + ((mat & 1) << 3) + rin) * 128 + 32 * kc + ((mat >> 1) << 4));
            ldsm4(a, qa[s][kc]);
        }

    float co[8][4];
#pragma unroll
    for (int j = 0; j < 8; j++)
#pragma unroll
        for (int r = 0; r < 4; r++) co[j][r] = 0.f;
    float lsA = 0.f, lsB = 0.f;

    for (int t = 0; t < S_LEN / 64; t++) {
        if (t > 0) { CP_WAIT0(); __syncthreads(); }
        if (t + 1 < S_LEN / 64) { load_kv(smb, b, t + 1, (t + 1) & 1, tid); CP_COMMIT(); }

        const uint32_t kbase = smb + K_OFF + (t & 1) * 8192;
        const uint32_t vbase = smb + V_OFF + (t & 1) * 8192;

        float sc[8][4];
#pragma unroll
        for (int j = 0; j < 8; j++)
#pragma unroll
            for (int r = 0; r < 4; r++) sc[j][r] = 0.f;

#pragma unroll
        for (int kc = 0; kc < 4; kc++) {
            uint32_t kb[3][4][4];
#pragma unroll
            for (int s = 0; s < 3; s++)
#pragma unroll
                for (int jj = 0; jj < 4; jj++) {
                    uint32_t a = kbase + s * 16384 +
                        SWZ((16 * jj + ((mat >> 1) << 3) + rin) * 128 + 32 * kc + ((mat & 1) << 4));
                    ldsm4(a, kb[s][jj]);
                }
            const int pa[6] = {0, 0, 1, 1, 0, 2};
            const int pb[6] = {0, 1, 0, 1, 2, 0};
#pragma unroll
            for (int p = 0; p < 6; p++)
#pragma unroll
                for (int j = 0; j < 8; j++)
                    mma16816(sc[j], qa[pa[p]][kc], &kb[pb[p]][j >> 1][(j & 1) * 2]);
        }

        uint32_t ph[4][4], pl[4][4];
#pragma unroll
        for (int j = 0; j < 8; j++) {
            int s0 = __float2int_rd(sc[j][0]); s0 = max(-124, min(60, s0));
            int s1 = __float2int_rd(sc[j][1]); s1 = max(-124, min(60, s1));
            int s2 = __float2int_rd(sc[j][2]); s2 = max(-124, min(60, s2));
            int s3 = __float2int_rd(sc[j][3]); s3 = max(-124, min(60, s3));
            float p0 = tbl[s0 + 124], p1 = tbl[s1 + 124];
            float p2 = tbl[s2 + 124], p3 = tbl[s3 + 124];
            lsA += p0 + p1;
            lsB += p2 + p3;
            int u = j >> 1, h2 = (j & 1) * 2;
            uint32_t w0 = pack_bf16(p0, p1), w1 = pack_bf16(p2, p3);
            ph[u][h2]     = w0;
            ph[u][h2 + 1] = w1;
            pl[u][h2]     = pack_bf16(p0 - bf16lo_f(w0), p1 - bf16hi_f(w0));
            pl[u][h2 + 1] = pack_bf16(p2 - bf16lo_f(w1), p3 - bf16hi_f(w1));
        }

#pragma unroll
        for (int u = 0; u < 4; u++) {
            uint32_t vb[2][4][4];
#pragma unroll
            for (int s = 0; s < 2; s++)
#pragma unroll
                for (int jj = 0; jj < 4; jj++) {
                    uint32_t a = vbase + s * 16384 +
                        SWZ((16 * u + ((mat & 1) << 3) + rin) * 128 + 32 * jj + ((mat >> 1) << 4));
                    ldsm4t(a, vb[s][jj]);
                }
#pragma unroll
            for (int j = 0; j < 8; j++) {
                mma16816(co[j], ph[u], &vb[0][j >> 1][(j & 1) * 2]);
                mma16816(co[j], ph[u], &vb[1][j >> 1][(j & 1) * 2]);
                mma16816(co[j], pl[u], &vb[0][j >> 1][(j & 1) * 2]);
            }
        }
    }

#pragma unroll
    for (int d = 1; d < 4; d <<= 1) {
        lsA += __shfl_xor_sync(0xffffffffu, lsA, d);
        lsB += __shfl_xor_sync(0xffffffffu, lsB, d);
    }
    const float invA = 1.0f / lsA;
    const float invB = 1.0f / lsB;

    const int g = lane >> 2, tq = lane & 3;
    float* oA = out + (size_t)(b * S_LEN + q0 + qrow0 + g) * H_SZ;
    float* oB = out + (size_t)(b * S_LEN + q0 + qrow0 + g + 8) * H_SZ;
#pragma unroll
    for (int j = 0; j < 8; j++) {
        int cb2 = 8 * j + 2 * tq;
        *reinterpret_cast<float2*>(oA + cb2) = make_float2(co[j][0] * invA, co[j][1] * invA);
        *reinterpret_cast<float2*>(oB + cb2) = make_float2(co[j][2] * invB, co[j][3] * invB);
    }
}

// ---------------------------------------------------------------------------
extern "C" void kernel_launch(void* const* d_in, const int* in_sizes, int n_in,
                              void* d_out, int out_size)
{
    const float* x  = (const float*)d_in[0];
    const float* Wq = (const float*)d_in[1];
    const float* Wk = (const float*)d_in[2];
    const float* Wv = (const float*)d_in[3];
    float* out = (float*)d_out;

    cudaFuncSetAttribute(qkv_mma_kernel, cudaFuncAttributeMaxDynamicSharedMemorySize, QKV_SMEM);
    cudaFuncSetAttribute(flash_kernel, cudaFuncAttributeMaxDynamicSharedMemorySize, FL_SMEM);

    prep_kernel<<<XBLK + 144, 256>>>(x, Wq, Wk, Wv);
    qkv_mma_kernel<<<dim3(128, 3), 256, QKV_SMEM>>>();
    flash_kernel<<<dim3(S_LEN / 128, B_SZ), 256, FL_SMEM>>>(out);
}